// round 6
// baseline (speedup 1.0000x reference)
#include <cuda_runtime.h>
#include <cuda_bf16.h>
#include <mma.h>
#include <cstdint>

using namespace nvcuda;

// ---------------------------------------------------------------------------
// GIN conv: out = (x + scatter_sum(x[src], dst)) @ W^T + b
//   x: [N,128] f32, edge_index: [2,E] int32 (JAX downcasts int64->int32!),
//   W: [128,128] f32, b: [128] f32
// K1: zero d_out (doubles as the aggregation buffer)
// K2: warp-per-edge gather + scalar atomicAdd scatter
// K3: in-place tiled tf32 wmma GEMM: out = (x + agg) @ W^T + b
// ---------------------------------------------------------------------------

#define CDIM 128
#define SMEM_STRIDE 132
#define GEMM_SMEM_BYTES (2 * 128 * SMEM_STRIDE * 4)   // 135168 B

// ---------------- K1: zero the aggregation buffer --------------------------
__global__ void zero_kernel(float4* __restrict__ p, int n4) {
    int i = blockIdx.x * blockDim.x + threadIdx.x;
    if (i < n4) p[i] = make_float4(0.f, 0.f, 0.f, 0.f);
}

// ---------------- K2: warp-per-edge scatter-add ----------------------------
__global__ void scatter_kernel(const float* __restrict__ x,
                               const int* __restrict__ ei,   // int32 indices
                               float* __restrict__ agg, int nE) {
    const int lane = threadIdx.x & 31;
    const int warpsPerGrid = (gridDim.x * blockDim.x) >> 5;
    int w = (blockIdx.x * blockDim.x + threadIdx.x) >> 5;

    for (; w < nE; w += warpsPerGrid) {
        int s = 0, d = 0;
        if (lane == 0) {
            s = __ldg(&ei[w]);
            d = __ldg(&ei[nE + w]);
        }
        s = __shfl_sync(0xffffffffu, s, 0);
        d = __shfl_sync(0xffffffffu, d, 0);

        float4 v = ((const float4*)(x + (size_t)s * CDIM))[lane];
        float* dst = agg + (size_t)d * CDIM + lane * 4;
        atomicAdd(dst + 0, v.x);
        atomicAdd(dst + 1, v.y);
        atomicAdd(dst + 2, v.z);
        atomicAdd(dst + 3, v.w);
    }
}

// ---------------- K3: tiled tf32 wmma GEMM, in place over d_out ------------
// Block: 256 threads = 8 warps. Tile: 128 rows x 128 cols, K = 128.
__global__ void gemm_kernel(const float* __restrict__ x,
                            float* __restrict__ out,     // in: agg, out: result
                            const float* __restrict__ W,
                            const float* __restrict__ bias,
                            int nRows) {
    extern __shared__ float smem[];
    float* As = smem;                       // [128][SMEM_STRIDE] tf32-rounded (x+agg)
    float* Ws = smem + 128 * SMEM_STRIDE;   // [128][SMEM_STRIDE] tf32-rounded W

    const int tid  = threadIdx.x;
    const int row0 = blockIdx.x * 128;

    // ---- fill smem: convert to tf32-representable floats ----
    for (int i = tid; i < 128 * 32; i += 256) {   // (row, 4-col group)
        int r  = i >> 5;
        int c4 = (i & 31) * 4;
        float4 xa = make_float4(0.f, 0.f, 0.f, 0.f);
        int grow = row0 + r;
        if (grow < nRows) {
            float4 xv = *(const float4*)(x   + (size_t)grow * CDIM + c4);
            float4 av = *(const float4*)(out + (size_t)grow * CDIM + c4);
            xa.x = xv.x + av.x; xa.y = xv.y + av.y;
            xa.z = xv.z + av.z; xa.w = xv.w + av.w;
        }
        float* p = As + r * SMEM_STRIDE + c4;
        p[0] = wmma::__float_to_tf32(xa.x);
        p[1] = wmma::__float_to_tf32(xa.y);
        p[2] = wmma::__float_to_tf32(xa.z);
        p[3] = wmma::__float_to_tf32(xa.w);

        float4 wv = *(const float4*)(W + r * CDIM + c4);
        float* q = Ws + r * SMEM_STRIDE + c4;
        q[0] = wmma::__float_to_tf32(wv.x);
        q[1] = wmma::__float_to_tf32(wv.y);
        q[2] = wmma::__float_to_tf32(wv.z);
        q[3] = wmma::__float_to_tf32(wv.w);
    }
    __syncthreads();

    const int warp = tid >> 5;
    const int mw = warp & 3;      // 32-row strip
    const int nw = warp >> 2;     // 64-col strip

    wmma::fragment<wmma::accumulator, 16, 16, 8, float> acc[2][4];
    #pragma unroll
    for (int mi = 0; mi < 2; mi++)
        #pragma unroll
        for (int ni = 0; ni < 4; ni++)
            wmma::fill_fragment(acc[mi][ni], 0.0f);

    #pragma unroll
    for (int k0 = 0; k0 < 128; k0 += 8) {
        wmma::fragment<wmma::matrix_a, 16, 16, 8, wmma::precision::tf32,
                       wmma::row_major> a_frag[2];
        #pragma unroll
        for (int mi = 0; mi < 2; mi++)
            wmma::load_matrix_sync(a_frag[mi],
                As + (32 * mw + 16 * mi) * SMEM_STRIDE + k0, SMEM_STRIDE);

        #pragma unroll
        for (int ni = 0; ni < 4; ni++) {
            // B[k][n] = W[n][k]: col_major view of W rows
            wmma::fragment<wmma::matrix_b, 16, 16, 8, wmma::precision::tf32,
                           wmma::col_major> b_frag;
            wmma::load_matrix_sync(b_frag,
                Ws + (64 * nw + 16 * ni) * SMEM_STRIDE + k0, SMEM_STRIDE);
            #pragma unroll
            for (int mi = 0; mi < 2; mi++)
                wmma::mma_sync(acc[mi][ni], a_frag[mi], b_frag, acc[mi][ni]);
        }
    }

    // ---- epilogue: stage through smem (reuse As), add bias, guarded write ----
    __syncthreads();
    #pragma unroll
    for (int mi = 0; mi < 2; mi++)
        #pragma unroll
        for (int ni = 0; ni < 4; ni++)
            wmma::store_matrix_sync(
                As + (32 * mw + 16 * mi) * SMEM_STRIDE + 64 * nw + 16 * ni,
                acc[mi][ni], SMEM_STRIDE, wmma::mem_row_major);
    __syncthreads();

    for (int i = tid; i < 128 * 32; i += 256) {
        int r  = i >> 5;
        int c4 = (i & 31) * 4;
        int grow = row0 + r;
        if (grow < nRows) {
            const float* p = As + r * SMEM_STRIDE + c4;
            float4 bv = *(const float4*)(bias + c4);
            float4 o;
            o.x = p[0] + bv.x; o.y = p[1] + bv.y;
            o.z = p[2] + bv.z; o.w = p[3] + bv.w;
            *(float4*)(out + (size_t)grow * CDIM + c4) = o;
        }
    }
}

// ---------------------------------------------------------------------------
extern "C" void kernel_launch(void* const* d_in, const int* in_sizes, int n_in,
                              void* d_out, int out_size) {
    const float* x  = (const float*)d_in[0];
    const int*   ei = (const int*)d_in[1];     // int32 (JAX x64 disabled)
    const float* W  = (const float*)d_in[2];
    const float* b  = (const float*)d_in[3];
    float*       out = (float*)d_out;

    int N  = in_sizes[0] / CDIM;   // 100000
    int nE = in_sizes[1] / 2;      // 600000

    // K1: zero agg buffer (= d_out)
    int n4 = N * (CDIM / 4);
    zero_kernel<<<(n4 + 255) / 256, 256>>>((float4*)out, n4);

    // K2: scatter-add, one warp per edge (grid-stride, 8 warps/block)
    int sblocks = (nE + 7) / 8;
    if (sblocks > 75000) sblocks = 75000;
    scatter_kernel<<<sblocks, 256>>>(x, ei, out, nE);

    // K3: GEMM with bias, in place
    cudaFuncSetAttribute(gemm_kernel, cudaFuncAttributeMaxDynamicSharedMemorySize,
                         GEMM_SMEM_BYTES);
    gemm_kernel<<<(N + 127) / 128, 256, GEMM_SMEM_BYTES>>>(x, out, W, b, N);
}

// round 7
// speedup vs baseline: 1.4518x; 1.4518x over previous
#include <cuda_runtime.h>
#include <cuda_bf16.h>
#include <mma.h>
#include <cstdint>

using namespace nvcuda;

// ---------------------------------------------------------------------------
// GIN conv: out = (x + scatter_sum(x[src], dst)) @ W^T + b
//   x: [N,128] f32, edge_index: [2,E] int32, W: [128,128] f32, b: [128] f32
// K1: copy x -> d_out (agg buffer pre-seeded with x, folds the "+x")
// K2: warp-per-edge gather + red.global.add.v4.f32 scatter
// K3: in-place tiled tf32 wmma GEMM: out = agg_rows @ W^T + b
// ---------------------------------------------------------------------------

#define CDIM 128
#define SMEM_STRIDE 132
#define GEMM_SMEM_BYTES (2 * 128 * SMEM_STRIDE * 4)   // 135168 B

// ---------------- K1: seed agg buffer with x -------------------------------
__global__ void copy_kernel(const float4* __restrict__ src,
                            float4* __restrict__ dst, int n4) {
    int i = blockIdx.x * blockDim.x + threadIdx.x;
    if (i < n4) dst[i] = src[i];
}

// ---------------- K2: warp-per-edge scatter-add (vector RED) ---------------
__global__ void scatter_kernel(const float* __restrict__ x,
                               const int* __restrict__ ei,   // int32 indices
                               float* __restrict__ agg, int nE) {
    const int lane = threadIdx.x & 31;
    const int warpsPerGrid = (gridDim.x * blockDim.x) >> 5;
    int w = (blockIdx.x * blockDim.x + threadIdx.x) >> 5;

    for (; w < nE; w += warpsPerGrid) {
        int s = 0, d = 0;
        if (lane == 0) {
            s = __ldg(&ei[w]);
            d = __ldg(&ei[nE + w]);
        }
        s = __shfl_sync(0xffffffffu, s, 0);
        d = __shfl_sync(0xffffffffu, d, 0);

        float4 v = ((const float4*)(x + (size_t)s * CDIM))[lane];
        float* dst = agg + (size_t)d * CDIM + lane * 4;
        asm volatile("red.global.add.v4.f32 [%0], {%1,%2,%3,%4};"
                     :: "l"(dst), "f"(v.x), "f"(v.y), "f"(v.z), "f"(v.w)
                     : "memory");
    }
}

// ---------------- K3: tiled tf32 wmma GEMM, in place over d_out ------------
// Block: 256 threads = 8 warps. Tile: 128 rows x 128 cols, K = 128.
// A rows (= x + agg) already live in `out`.
__global__ void gemm_kernel(float* __restrict__ out,      // in: x+agg, out: result
                            const float* __restrict__ W,
                            const float* __restrict__ bias,
                            int nRows) {
    extern __shared__ float smem[];
    float* As = smem;                       // [128][SMEM_STRIDE]
    float* Ws = smem + 128 * SMEM_STRIDE;   // [128][SMEM_STRIDE]

    const int tid  = threadIdx.x;
    const int row0 = blockIdx.x * 128;

    // ---- fill smem: convert to tf32-representable floats ----
    for (int i = tid; i < 128 * 32; i += 256) {   // (row, 4-col group)
        int r  = i >> 5;
        int c4 = (i & 31) * 4;
        float4 xa = make_float4(0.f, 0.f, 0.f, 0.f);
        int grow = row0 + r;
        if (grow < nRows)
            xa = *(const float4*)(out + (size_t)grow * CDIM + c4);
        float* p = As + r * SMEM_STRIDE + c4;
        p[0] = wmma::__float_to_tf32(xa.x);
        p[1] = wmma::__float_to_tf32(xa.y);
        p[2] = wmma::__float_to_tf32(xa.z);
        p[3] = wmma::__float_to_tf32(xa.w);

        float4 wv = *(const float4*)(W + r * CDIM + c4);
        float* q = Ws + r * SMEM_STRIDE + c4;
        q[0] = wmma::__float_to_tf32(wv.x);
        q[1] = wmma::__float_to_tf32(wv.y);
        q[2] = wmma::__float_to_tf32(wv.z);
        q[3] = wmma::__float_to_tf32(wv.w);
    }
    __syncthreads();

    const int warp = tid >> 5;
    const int mw = warp & 3;      // 32-row strip
    const int nw = warp >> 2;     // 64-col strip

    wmma::fragment<wmma::accumulator, 16, 16, 8, float> acc[2][4];
    #pragma unroll
    for (int mi = 0; mi < 2; mi++)
        #pragma unroll
        for (int ni = 0; ni < 4; ni++)
            wmma::fill_fragment(acc[mi][ni], 0.0f);

    #pragma unroll
    for (int k0 = 0; k0 < 128; k0 += 8) {
        wmma::fragment<wmma::matrix_a, 16, 16, 8, wmma::precision::tf32,
                       wmma::row_major> a_frag[2];
        #pragma unroll
        for (int mi = 0; mi < 2; mi++)
            wmma::load_matrix_sync(a_frag[mi],
                As + (32 * mw + 16 * mi) * SMEM_STRIDE + k0, SMEM_STRIDE);

        #pragma unroll
        for (int ni = 0; ni < 4; ni++) {
            wmma::fragment<wmma::matrix_b, 16, 16, 8, wmma::precision::tf32,
                           wmma::col_major> b_frag;
            wmma::load_matrix_sync(b_frag,
                Ws + (64 * nw + 16 * ni) * SMEM_STRIDE + k0, SMEM_STRIDE);
            #pragma unroll
            for (int mi = 0; mi < 2; mi++)
                wmma::mma_sync(acc[mi][ni], a_frag[mi], b_frag, acc[mi][ni]);
        }
    }

    // ---- epilogue: stage through smem (reuse As), add bias, guarded write ----
    __syncthreads();
    #pragma unroll
    for (int mi = 0; mi < 2; mi++)
        #pragma unroll
        for (int ni = 0; ni < 4; ni++)
            wmma::store_matrix_sync(
                As + (32 * mw + 16 * mi) * SMEM_STRIDE + 64 * nw + 16 * ni,
                acc[mi][ni], SMEM_STRIDE, wmma::mem_row_major);
    __syncthreads();

    for (int i = tid; i < 128 * 32; i += 256) {
        int r  = i >> 5;
        int c4 = (i & 31) * 4;
        int grow = row0 + r;
        if (grow < nRows) {
            const float* p = As + r * SMEM_STRIDE + c4;
            float4 bv = *(const float4*)(bias + c4);
            float4 o;
            o.x = p[0] + bv.x; o.y = p[1] + bv.y;
            o.z = p[2] + bv.z; o.w = p[3] + bv.w;
            *(float4*)(out + (size_t)grow * CDIM + c4) = o;
        }
    }
}

// ---------------------------------------------------------------------------
extern "C" void kernel_launch(void* const* d_in, const int* in_sizes, int n_in,
                              void* d_out, int out_size) {
    const float* x  = (const float*)d_in[0];
    const int*   ei = (const int*)d_in[1];     // int32 (JAX x64 disabled)
    const float* W  = (const float*)d_in[2];
    const float* b  = (const float*)d_in[3];
    float*       out = (float*)d_out;

    int N  = in_sizes[0] / CDIM;   // 100000
    int nE = in_sizes[1] / 2;      // 600000

    // K1: seed agg buffer with x (folds the "+x" term)
    int n4 = N * (CDIM / 4);
    copy_kernel<<<(n4 + 255) / 256, 256>>>((const float4*)x, (float4*)out, n4);

    // K2: scatter-add, one warp per edge (grid-stride, 8 warps/block)
    int sblocks = (nE + 7) / 8;
    if (sblocks > 75000) sblocks = 75000;
    scatter_kernel<<<sblocks, 256>>>(x, ei, out, nE);

    // K3: GEMM with bias, in place
    cudaFuncSetAttribute(gemm_kernel, cudaFuncAttributeMaxDynamicSharedMemorySize,
                         GEMM_SMEM_BYTES);
    gemm_kernel<<<(N + 127) / 128, 256, GEMM_SMEM_BYTES>>>(out, W, b, N);
}

// round 8
// speedup vs baseline: 1.7143x; 1.1808x over previous
#include <cuda_runtime.h>
#include <cuda_bf16.h>
#include <mma.h>
#include <cstdint>

using namespace nvcuda;

// ---------------------------------------------------------------------------
// GIN conv: out = (x + scatter_sum(x[src], dst)) @ W^T + b
//   x: [N,128] f32, edge_index: [2,E] int32, W: [128,128] f32, b: [128] f32
// CSR two-phase aggregation (no float atomics):
//   K1 zero degree, K2 histogram(dst), K3-K5 exclusive scan -> offsets,
//   K6 fill src-per-dst lists (int atomics), K7 warp-per-node gather-sum
//   (acc seeded with x[node], written to d_out), K8 in-place tf32 wmma GEMM.
// ---------------------------------------------------------------------------

#define CDIM 128
#define SMEM_STRIDE 132
#define GEMM_SMEM_BYTES (2 * 128 * SMEM_STRIDE * 4)   // 135168 B

#define N_MAX 131072
#define E_MAX 650000
#define SCAN_B 1024
#define SCAN_MAXBLKS 128          // ceil(N_MAX/SCAN_B) = 128

__device__ int g_deg[N_MAX + 1];      // degree, then reused as fill cursor
__device__ int g_offs[N_MAX + 1];     // CSR offsets
__device__ int g_srcs[E_MAX];         // src node per dst-grouped edge
__device__ int g_bsum[SCAN_MAXBLKS];  // per-block scan partials

// ---------------- K1: zero degree array ------------------------------------
__global__ void zero_deg_kernel(int n) {
    int i = blockIdx.x * blockDim.x + threadIdx.x;
    if (i <= n) g_deg[i] = 0;
}

// ---------------- K2: degree histogram over dst ----------------------------
__global__ void hist_kernel(const int* __restrict__ ei, int nE) {
    int i = blockIdx.x * blockDim.x + threadIdx.x;
    if (i < nE) atomicAdd(&g_deg[ei[nE + i]], 1);
}

// ---------------- K3: block-level exclusive scan ---------------------------
__global__ void scan1_kernel(int n) {
    __shared__ int sm[SCAN_B];
    int i = blockIdx.x * SCAN_B + threadIdx.x;
    int v = (i < n) ? g_deg[i] : 0;
    sm[threadIdx.x] = v;
    __syncthreads();
    for (int off = 1; off < SCAN_B; off <<= 1) {
        int t = (threadIdx.x >= off) ? sm[threadIdx.x - off] : 0;
        __syncthreads();
        sm[threadIdx.x] += t;
        __syncthreads();
    }
    if (i < n) g_offs[i] = sm[threadIdx.x] - v;        // exclusive
    if (threadIdx.x == SCAN_B - 1) g_bsum[blockIdx.x] = sm[SCAN_B - 1];
}

// ---------------- K4: scan the block partials (single block) ---------------
__global__ void scan2_kernel(int nb) {
    __shared__ int sm[SCAN_MAXBLKS];
    int v = (threadIdx.x < nb) ? g_bsum[threadIdx.x] : 0;
    sm[threadIdx.x] = v;
    __syncthreads();
    for (int off = 1; off < SCAN_MAXBLKS; off <<= 1) {
        int t = (threadIdx.x >= off) ? sm[threadIdx.x - off] : 0;
        __syncthreads();
        sm[threadIdx.x] += t;
        __syncthreads();
    }
    if (threadIdx.x < nb) g_bsum[threadIdx.x] = sm[threadIdx.x] - v;  // exclusive
}

// ---------------- K5: add block offsets; init cursor; cap offs[n] ----------
__global__ void scan3_kernel(int n, int nE) {
    int i = blockIdx.x * SCAN_B + threadIdx.x;
    if (i < n) {
        int o = g_offs[i] + g_bsum[blockIdx.x];
        g_offs[i] = o;
        g_deg[i]  = o;                 // cursor for fill
    }
    if (i == 0) g_offs[n] = nE;
}

// ---------------- K6: fill CSR src lists (int atomics only) ----------------
__global__ void fill_kernel(const int* __restrict__ ei, int nE) {
    int i = blockIdx.x * blockDim.x + threadIdx.x;
    if (i < nE) {
        int s = ei[i];
        int d = ei[nE + i];
        int pos = atomicAdd(&g_deg[d], 1);
        g_srcs[pos] = s;
    }
}

// ---------------- K7: warp-per-node gather-sum (out = x + agg) -------------
__global__ void gather_kernel(const float4* __restrict__ x4,
                              float4* __restrict__ out4, int n) {
    int warp = (blockIdx.x * blockDim.x + threadIdx.x) >> 5;
    int lane = threadIdx.x & 31;
    if (warp >= n) return;

    int beg = g_offs[warp];
    int end = g_offs[warp + 1];
    float4 acc = x4[(size_t)warp * 32 + lane];

    for (int base = beg; base < end; base += 32) {
        int cnt = end - base; if (cnt > 32) cnt = 32;
        int sl = (lane < cnt) ? __ldg(&g_srcs[base + lane]) : 0;
        for (int j = 0; j < cnt; j++) {
            int s = __shfl_sync(0xffffffffu, sl, j);
            float4 v = x4[(size_t)s * 32 + lane];
            acc.x += v.x; acc.y += v.y; acc.z += v.z; acc.w += v.w;
        }
    }
    out4[(size_t)warp * 32 + lane] = acc;
}

// ---------------- K8: tiled tf32 wmma GEMM, in place over d_out ------------
__global__ void gemm_kernel(float* __restrict__ out,      // in: x+agg, out: result
                            const float* __restrict__ W,
                            const float* __restrict__ bias,
                            int nRows) {
    extern __shared__ float smem[];
    float* As = smem;                       // [128][SMEM_STRIDE]
    float* Ws = smem + 128 * SMEM_STRIDE;   // [128][SMEM_STRIDE]

    const int tid  = threadIdx.x;
    const int row0 = blockIdx.x * 128;

    for (int i = tid; i < 128 * 32; i += 256) {   // (row, 4-col group)
        int r  = i >> 5;
        int c4 = (i & 31) * 4;
        float4 xa = make_float4(0.f, 0.f, 0.f, 0.f);
        int grow = row0 + r;
        if (grow < nRows)
            xa = *(const float4*)(out + (size_t)grow * CDIM + c4);
        float* p = As + r * SMEM_STRIDE + c4;
        p[0] = wmma::__float_to_tf32(xa.x);
        p[1] = wmma::__float_to_tf32(xa.y);
        p[2] = wmma::__float_to_tf32(xa.z);
        p[3] = wmma::__float_to_tf32(xa.w);

        float4 wv = *(const float4*)(W + r * CDIM + c4);
        float* q = Ws + r * SMEM_STRIDE + c4;
        q[0] = wmma::__float_to_tf32(wv.x);
        q[1] = wmma::__float_to_tf32(wv.y);
        q[2] = wmma::__float_to_tf32(wv.z);
        q[3] = wmma::__float_to_tf32(wv.w);
    }
    __syncthreads();

    const int warp = tid >> 5;
    const int mw = warp & 3;
    const int nw = warp >> 2;

    wmma::fragment<wmma::accumulator, 16, 16, 8, float> acc[2][4];
    #pragma unroll
    for (int mi = 0; mi < 2; mi++)
        #pragma unroll
        for (int ni = 0; ni < 4; ni++)
            wmma::fill_fragment(acc[mi][ni], 0.0f);

    #pragma unroll
    for (int k0 = 0; k0 < 128; k0 += 8) {
        wmma::fragment<wmma::matrix_a, 16, 16, 8, wmma::precision::tf32,
                       wmma::row_major> a_frag[2];
        #pragma unroll
        for (int mi = 0; mi < 2; mi++)
            wmma::load_matrix_sync(a_frag[mi],
                As + (32 * mw + 16 * mi) * SMEM_STRIDE + k0, SMEM_STRIDE);

        #pragma unroll
        for (int ni = 0; ni < 4; ni++) {
            wmma::fragment<wmma::matrix_b, 16, 16, 8, wmma::precision::tf32,
                           wmma::col_major> b_frag;
            wmma::load_matrix_sync(b_frag,
                Ws + (64 * nw + 16 * ni) * SMEM_STRIDE + k0, SMEM_STRIDE);
            #pragma unroll
            for (int mi = 0; mi < 2; mi++)
                wmma::mma_sync(acc[mi][ni], a_frag[mi], b_frag, acc[mi][ni]);
        }
    }

    __syncthreads();
    #pragma unroll
    for (int mi = 0; mi < 2; mi++)
        #pragma unroll
        for (int ni = 0; ni < 4; ni++)
            wmma::store_matrix_sync(
                As + (32 * mw + 16 * mi) * SMEM_STRIDE + 64 * nw + 16 * ni,
                acc[mi][ni], SMEM_STRIDE, wmma::mem_row_major);
    __syncthreads();

    for (int i = tid; i < 128 * 32; i += 256) {
        int r  = i >> 5;
        int c4 = (i & 31) * 4;
        int grow = row0 + r;
        if (grow < nRows) {
            const float* p = As + r * SMEM_STRIDE + c4;
            float4 bv = *(const float4*)(bias + c4);
            float4 o;
            o.x = p[0] + bv.x; o.y = p[1] + bv.y;
            o.z = p[2] + bv.z; o.w = p[3] + bv.w;
            *(float4*)(out + (size_t)grow * CDIM + c4) = o;
        }
    }
}

// ---------------------------------------------------------------------------
extern "C" void kernel_launch(void* const* d_in, const int* in_sizes, int n_in,
                              void* d_out, int out_size) {
    const float* x  = (const float*)d_in[0];
    const int*   ei = (const int*)d_in[1];     // int32 (JAX x64 disabled)
    const float* W  = (const float*)d_in[2];
    const float* b  = (const float*)d_in[3];
    float*       out = (float*)d_out;

    int N  = in_sizes[0] / CDIM;   // 100000
    int nE = in_sizes[1] / 2;      // 600000

    int scanBlks = (N + SCAN_B - 1) / SCAN_B;          // 98 for N=100000

    zero_deg_kernel<<<(N + 256) / 256, 256>>>(N);
    hist_kernel<<<(nE + 255) / 256, 256>>>(ei, nE);
    scan1_kernel<<<scanBlks, SCAN_B>>>(N);
    scan2_kernel<<<1, SCAN_MAXBLKS>>>(scanBlks);
    scan3_kernel<<<scanBlks, SCAN_B>>>(N, nE);
    fill_kernel<<<(nE + 255) / 256, 256>>>(ei, nE);

    gather_kernel<<<(N * 32 + 255) / 256, 256>>>((const float4*)x, (float4*)out, N);

    cudaFuncSetAttribute(gemm_kernel, cudaFuncAttributeMaxDynamicSharedMemorySize,
                         GEMM_SMEM_BYTES);
    gemm_kernel<<<(N + 127) / 128, 256, GEMM_SMEM_BYTES>>>(out, W, b, N);
}